// round 1
// baseline (speedup 1.0000x reference)
#include <cuda_runtime.h>
#include <math.h>

// Problem constants
#define Bn   8
#define Cn   64
#define Hn   32
#define Wn   32
#define HWn  1024
#define NEGn 256
#define EPSc 1e-8f

// ---------------- scratch (device globals; no allocation in kernel_launch) ---
__device__ __align__(16) float  g_z1t[Bn * HWn * Cn];   // 2 MB, pixel-major z1
__device__ __align__(16) float  g_z2t[Bn * HWn * Cn];   // 2 MB, pixel-major z2
__device__ float  g_z1n [Bn * HWn];
__device__ float  g_z1sq[Bn * HWn];
__device__ float  g_z2n [Bn * HWn];
__device__ __align__(16) float4 g_imgt[HWn];            // (r,g,b,0) per pixel
__device__ float  g_pn  [Bn * 16 * NEGn];               // per-block partial sim_neg sums
__device__ float  g_s0p [Bn * 16];                      // per-block partial sim0 sums

// ---------------- prep: transpose views to pixel-major + per-pixel norms -----
__global__ void prep_transpose(const float* __restrict__ z1,
                               const float* __restrict__ z2) {
    __shared__ float ts[64][33];
    const int b  = blockIdx.y;
    const int q0 = blockIdx.x * 32;
    const int t  = threadIdx.x;  // 256 threads

    #pragma unroll
    for (int s = 0; s < 2; s++) {
        const float* zp  = s ? z2 : z1;
        float*       outp = s ? g_z2t : g_z1t;

        // coalesced load of a (64 c) x (32 q) tile
        #pragma unroll
        for (int k = 0; k < 8; k++) {
            int idx = k * 256 + t;
            int c = idx >> 5, j = idx & 31;
            ts[c][j] = zp[((b * 64 + c) << 10) + q0 + j];
        }
        __syncthreads();

        // per-pixel squared norms (threads 0..31, conflict-free column reads)
        if (t < 32) {
            float sum = 0.f;
            #pragma unroll
            for (int c = 0; c < 64; c++) { float v = ts[c][t]; sum += v * v; }
            int gi = (b << 10) + q0 + t;
            if (s == 0) { g_z1sq[gi] = sum; g_z1n[gi] = sqrtf(sum); }
            else        { g_z2n[gi] = sqrtf(sum); }
        }

        // coalesced transposed store: row = pixel, 64 contiguous channels
        #pragma unroll
        for (int k = 0; k < 8; k++) {
            int idx = k * 256 + t;
            int j = idx >> 6, c = idx & 63;
            outp[(((b << 10) + q0 + j) << 6) + c] = ts[c][j];
        }
        __syncthreads();
    }
}

__global__ void prep_img(const float* __restrict__ img) {
    int q = blockIdx.x * 256 + threadIdx.x;  // 1024 pixels
    g_imgt[q] = make_float4(img[q], img[HWn + q], img[2 * HWn + q], 0.f);
}

// ---------------- main kernel -------------------------------------------------
// grid (B, 16), 512 threads. Block handles 64 p's: 16 warps x 4 p each.
// Warp processes one p at a time:
//   phase1: load 256 (nh,nw), build q table, accumulate eucsq/rgbsq -> weight
//   phase2: octet-cooperative gathered dot over 256 negs (2 wavefronts/neg)
//   phase3: cos -> min(|cos*w|,1), accumulate per-n sums in registers
__global__ void __launch_bounds__(512, 1)
main_kernel(const int* __restrict__ neg_idx) {
    __shared__ float4         imgt_sm[HWn];       // 16 KB
    __shared__ float          z2n_sm [HWn];       //  4 KB
    __shared__ unsigned short q_sm [16][NEGn];    //  8 KB
    __shared__ float          dot_sm[16][NEGn];   // 16 KB
    __shared__ float          s0w[16];

    const int b    = blockIdx.x;
    const int by   = blockIdx.y;
    const int t    = threadIdx.x;
    const int w    = t >> 5;
    const int lane = t & 31;
    const int m    = lane & 7;   // channel slot within octet
    const int o    = lane >> 3;  // neg slot within group of 4

    for (int i = t; i < HWn; i += 512) {
        imgt_sm[i] = g_imgt[i];
        z2n_sm[i]  = g_z2n[(b << 10) + i];
    }
    __syncthreads();

    const float INV_EUC   = 1.0f / sqrtf((float)((Hn - 1) * (Hn - 1) + (Wn - 1) * (Wn - 1)));
    const float INV_SQRT3 = 0.57735026919f;

    float acc[8];
    #pragma unroll
    for (int r = 0; r < 8; r++) acc[r] = 0.f;
    float sim0acc = 0.f;

    const float4* z2base = (const float4*)g_z2t + ((size_t)(b << 10) << 4);

    #pragma unroll 1
    for (int it = 0; it < 4; it++) {
        const int p = (by << 6) + (w << 2) + it;

        // z1 channels for this lane: {4m..4m+3} and {32+4m..32+4m+3}
        const float4* z1row = (const float4*)g_z1t + (((size_t)(b << 10) + p) << 4);
        const float4 z1a = z1row[m];
        const float4 z1b = z1row[8 + m];
        const float  z1np  = g_z1n [(b << 10) + p];
        const float  z1sqp = g_z1sq[(b << 10) + p];

        const float hp = (float)(p >> 5), wp = (float)(p & 31);
        const float4 ctr = imgt_sm[p];

        const int* negH = neg_idx + ((size_t)(b * 2) << 18) + (p << 8);
        const int* negW = negH + (1 << 18);

        // ---- phase 1: indices + weight ----
        float eucsq = 0.f, rgbsq = 0.f;
        #pragma unroll
        for (int r = 0; r < 8; r++) {
            int n  = (r << 5) + lane;
            int nh = negH[n];
            int nw = negW[n];
            int q  = (nh << 5) + nw;
            q_sm[w][n] = (unsigned short)q;
            float dh = hp - (float)nh, dw = wp - (float)nw;
            eucsq += dh * dh; eucsq += dw * dw;
            float4 c4 = imgt_sm[q];
            float dr = ctr.x - c4.x, dg = ctr.y - c4.y, db = ctr.z - c4.z;
            rgbsq += dr * dr; rgbsq += dg * dg; rgbsq += db * db;
        }
        #pragma unroll
        for (int s = 16; s > 0; s >>= 1) {
            eucsq += __shfl_xor_sync(0xffffffffu, eucsq, s);
            rgbsq += __shfl_xor_sync(0xffffffffu, rgbsq, s);
        }
        const float weight = 0.8f * sqrtf(eucsq) * INV_EUC
                           + 0.2f * sqrtf(rgbsq) * INV_SQRT3;
        __syncwarp();

        // ---- phase 2: gathered dot, 4 negs per warp step ----
        #pragma unroll 4
        for (int g = 0; g < 64; g++) {
            int myneg = (g << 2) + o;
            int q = q_sm[w][myneg];
            const float4* row = z2base + (q << 4);
            float4 a  = row[m];
            float4 bb = row[8 + m];
            float d = a.x * z1a.x + a.y * z1a.y + a.z * z1a.z + a.w * z1a.w
                    + bb.x * z1b.x + bb.y * z1b.y + bb.z * z1b.z + bb.w * z1b.w;
            d += __shfl_xor_sync(0xffffffffu, d, 4);
            d += __shfl_xor_sync(0xffffffffu, d, 2);
            d += __shfl_xor_sync(0xffffffffu, d, 1);
            if (m == 0) dot_sm[w][myneg] = d;
        }
        __syncwarp();

        // ---- phase 3: cos / clamp / accumulate (lane owns n = r*32+lane) ----
        #pragma unroll
        for (int r = 0; r < 8; r++) {
            int n = (r << 5) + lane;
            float d   = dot_sm[w][n];
            int   q   = q_sm[w][n];
            float pnn = z2n_sm[q];
            float den = fmaxf(z1np * pnn, EPSc);
            float cosv = __fdividef(d, den);
            float s = fminf(fabsf(cosv * weight), 1.0f);
            acc[r] += s;
        }
        if (lane == 0) {
            float c0 = z1sqp / fmaxf(z1sqp, EPSc);
            sim0acc += fminf(fabsf(c0), 1.0f);
        }
        __syncwarp();
    }

    // ---- deterministic block-level reduction of per-n sums ----
    __syncthreads();                 // all warps done with dot_sm
    #pragma unroll
    for (int r = 0; r < 8; r++) dot_sm[w][(r << 5) + lane] = acc[r];
    if (lane == 0) s0w[w] = sim0acc;
    __syncthreads();

    if (t < NEGn) {
        float s = 0.f;
        #pragma unroll
        for (int k = 0; k < 16; k++) s += dot_sm[k][t];
        g_pn[(((b << 4) + by) << 8) + t] = s;
    }
    if (t == 0) {
        float s = 0.f;
        #pragma unroll
        for (int k = 0; k < 16; k++) s += s0w[k];
        g_s0p[(b << 4) + by] = s;
    }
}

// ---------------- final reduction: 1 block, 256 threads ----------------------
__global__ void final_kernel(float* __restrict__ out, int out_size) {
    const int t = threadIdx.x;
    __shared__ float r1[8], r2[8];
    float loss = 0.f, o1 = 0.f, o2 = 0.f;

    for (int b = 0; b < Bn; b++) {
        float sn_sum = 0.f;
        #pragma unroll
        for (int k = 0; k < 16; k++) sn_sum += g_pn[(((b << 4) + k) << 8) + t];
        float sn  = sn_sum * (1.0f / 1024.0f) * 0.5f;   // mean over p, / TEMP
        float l1m = fmaxf(log1pf(-sn), -100.0f);

        float v1 = l1m, v2 = sn;
        #pragma unroll
        for (int s = 16; s > 0; s >>= 1) {
            v1 += __shfl_xor_sync(0xffffffffu, v1, s);
            v2 += __shfl_xor_sync(0xffffffffu, v2, s);
        }
        if ((t & 31) == 0) { r1[t >> 5] = v1; r2[t >> 5] = v2; }
        __syncthreads();
        if (t == 0) {
            float s1 = 0.f, s2 = 0.f;
            #pragma unroll
            for (int i = 0; i < 8; i++) { s1 += r1[i]; s2 += r2[i]; }
            float s0sum = 0.f;
            #pragma unroll
            for (int k = 0; k < 16; k++) s0sum += g_s0p[(b << 4) + k];
            float s0   = s0sum * (1.0f / 1024.0f);
            float logp = fmaxf(logf(s0), -100.0f);
            loss += -(logp + s1) * (1.0f / 257.0f);
            o1 += s0;
            o2 += s2;
        }
        __syncthreads();
    }

    if (t == 0) {
        if (out_size > 0) out[0] = loss * 0.125f;                       // mean bce
        if (out_size > 1) out[1] = o1 * 0.125f;                         // sim_all[0]/B
        if (out_size > 2) out[2] = o2 * (2.0f / (256.0f * 8.0f));       // sum/NEG*TEMP/B
    }
}

// ---------------- launch ------------------------------------------------------
extern "C" void kernel_launch(void* const* d_in, const int* in_sizes, int n_in,
                              void* d_out, int out_size) {
    const float* v1   = (const float*)d_in[0];   // views_1 (8,64,32,32)
    const float* v2   = (const float*)d_in[1];   // views_2 (8,64,32,32)
    const float* img  = (const float*)d_in[2];   // img     (1,3,32,32)
    const int*   nidx = (const int*)  d_in[3];   // neg_idx (8,2,1024,256)

    prep_transpose<<<dim3(32, 8), 256>>>(v1, v2);
    prep_img<<<4, 256>>>(img);
    main_kernel<<<dim3(Bn, 16), 512>>>(nidx);
    final_kernel<<<1, 256>>>((float*)d_out, out_size);
}

// round 2
// speedup vs baseline: 1.9954x; 1.9954x over previous
#include <cuda_runtime.h>
#include <math.h>

// Problem constants
#define Bn   8
#define Cn   64
#define Hn   32
#define Wn   32
#define HWn  1024
#define NEGn 256

// ---------------- scratch (device globals) -----------------------------------
__device__ __align__(16) float    g_z1t[Bn * HWn * Cn];     // 2 MB, pixel-major z1 (fp32)
__device__ __align__(16) unsigned g_z2b[Bn * HWn * 32];     // 1 MB, pixel-major z2, bf16x2 packed (32 uints = 128B/row)
__device__ float  g_rz1n[Bn * HWn];                          // 1/||z1_p||
__device__ float  g_z1sq[Bn * HWn];
__device__ float  g_rz2n[Bn * HWn];                          // 1/||z2_q||
__device__ __align__(16) float4 g_imgt[HWn];                 // (r,g,b,0) per pixel
__device__ float  g_pn  [Bn * 16 * NEGn];                    // per-block partial sim_neg sums
__device__ float  g_s0p [Bn * 16];                           // per-block partial sim0 sums

// round-to-nearest-even fp32 -> bf16 bits
__device__ __forceinline__ unsigned bf16rn(float f) {
    unsigned u = __float_as_uint(f);
    return (u + 0x7FFFu + ((u >> 16) & 1u)) >> 16;
}

// ---------------- prep: transpose + norms + img table ------------------------
__global__ void prep_transpose(const float* __restrict__ z1,
                               const float* __restrict__ z2,
                               const float* __restrict__ img) {
    __shared__ float ts[64][33];
    const int b  = blockIdx.y;
    const int q0 = blockIdx.x * 32;
    const int t  = threadIdx.x;  // 256 threads

    // img table (only b==0 blocks; 32 pixels each)
    if (b == 0 && t < 32) {
        int q = q0 + t;
        g_imgt[q] = make_float4(img[q], img[HWn + q], img[2 * HWn + q], 0.f);
    }

    #pragma unroll
    for (int s = 0; s < 2; s++) {
        const float* zp = s ? z2 : z1;

        // coalesced load of (64 c) x (32 q) tile
        #pragma unroll
        for (int k = 0; k < 8; k++) {
            int idx = k * 256 + t;
            int c = idx >> 5, j = idx & 31;
            ts[c][j] = zp[((b * 64 + c) << 10) + q0 + j];
        }
        __syncthreads();

        // per-pixel norms from fp32 values
        if (t < 32) {
            float sum = 0.f;
            #pragma unroll
            for (int c = 0; c < 64; c++) { float v = ts[c][t]; sum += v * v; }
            int gi = (b << 10) + q0 + t;
            if (s == 0) { g_z1sq[gi] = sum; g_rz1n[gi] = rsqrtf(sum); }
            else        { g_rz2n[gi] = rsqrtf(sum); }
        }

        if (s == 0) {
            // z1: fp32 pixel-major store
            #pragma unroll
            for (int k = 0; k < 8; k++) {
                int idx = k * 256 + t;
                int j = idx >> 6, c = idx & 63;
                g_z1t[(((b << 10) + q0 + j) << 6) + c] = ts[c][j];
            }
        } else {
            // z2: bf16x2-packed pixel-major store (32 uints per pixel row)
            #pragma unroll
            for (int k = 0; k < 4; k++) {
                int idx = k * 256 + t;          // 0..1023 = 32 q x 32 channel-pairs
                int j = idx >> 5, cp = idx & 31;
                unsigned lo = bf16rn(ts[2 * cp][j]);
                unsigned hi = bf16rn(ts[2 * cp + 1][j]);
                g_z2b[(((b << 10) + q0 + j) << 5) + cp] = lo | (hi << 16);
            }
        }
        __syncthreads();
    }
}

// ---------------- main kernel -------------------------------------------------
// grid (B, 16), 1024 threads = 32 warps; each warp handles 2 p's.
__global__ void __launch_bounds__(1024, 1)
main_kernel(const int* __restrict__ neg_idx) {
    __shared__ float4         imgt_sm[HWn];       // 16 KB
    __shared__ float          rz2n_sm[HWn];       //  4 KB
    __shared__ unsigned short q_sm [32][NEGn];    // 16 KB
    __shared__ float          dot_sm[32][NEGn];   // 32 KB
    __shared__ float          s0w[32];

    const int b    = blockIdx.x;
    const int by   = blockIdx.y;
    const int t    = threadIdx.x;
    const int w    = t >> 5;
    const int lane = t & 31;
    const int m    = lane & 7;   // channel-octet slot
    const int o    = lane >> 3;  // neg slot within group of 4

    for (int i = t; i < HWn; i += 1024) {
        imgt_sm[i] = g_imgt[i];
        rz2n_sm[i] = g_rz2n[(b << 10) + i];
    }
    __syncthreads();

    const float INV_EUC   = 1.0f / sqrtf((float)((Hn - 1) * (Hn - 1) + (Wn - 1) * (Wn - 1)));
    const float INV_SQRT3 = 0.57735026919f;

    float acc[8];
    #pragma unroll
    for (int r = 0; r < 8; r++) acc[r] = 0.f;
    float sim0acc = 0.f;

    // lane-fixed base into the bf16 z2 table: row q = z2l[q*8] (uint4 = 16B, 8 per 128B row)
    const uint4* z2l = ((const uint4*)g_z2b) + ((size_t)b << 13) + m;

    #pragma unroll 1
    for (int it = 0; it < 2; it++) {
        const int p = (by << 6) + (w << 1) + it;

        // z1 channels 8m..8m+7 for this lane
        const float4* z1row = (const float4*)g_z1t + (((size_t)(b << 10) + p) << 4);
        const float4 z1a = z1row[2 * m];
        const float4 z1b = z1row[2 * m + 1];
        const float  rz1np = g_rz1n[(b << 10) + p];
        const float  z1sqp = g_z1sq[(b << 10) + p];

        const float hp = (float)(p >> 5), wp = (float)(p & 31);
        const float4 ctr = imgt_sm[p];

        const int* negH = neg_idx + ((size_t)(b * 2) << 18) + (p << 8);
        const int* negW = negH + (1 << 18);

        // ---- phase 1: indices + weight ----
        float eucsq = 0.f, rgbsq = 0.f;
        #pragma unroll
        for (int r = 0; r < 8; r++) {
            int n  = (r << 5) + lane;
            int nh = negH[n];
            int nw = negW[n];
            int q  = (nh << 5) + nw;
            q_sm[w][n] = (unsigned short)q;
            float dh = hp - (float)nh, dw = wp - (float)nw;
            eucsq += dh * dh; eucsq += dw * dw;
            float4 c4 = imgt_sm[q];
            float dr = ctr.x - c4.x, dg = ctr.y - c4.y, db = ctr.z - c4.z;
            rgbsq += dr * dr; rgbsq += dg * dg; rgbsq += db * db;
        }
        #pragma unroll
        for (int s = 16; s > 0; s >>= 1) {
            eucsq += __shfl_xor_sync(0xffffffffu, eucsq, s);
            rgbsq += __shfl_xor_sync(0xffffffffu, rgbsq, s);
        }
        const float weight = 0.8f * sqrtf(eucsq) * INV_EUC
                           + 0.2f * sqrtf(rgbsq) * INV_SQRT3;
        __syncwarp();

        // ---- phase 2: bf16 gathered dot, 4 negs per warp step, 1 line/neg ----
        #pragma unroll 4
        for (int g = 0; g < 64; g++) {
            int myneg = (g << 2) + o;
            int q = q_sm[w][myneg];
            uint4 v = z2l[q << 3];
            float d;
            d  = __uint_as_float(v.x << 16)          * z1a.x;
            d += __uint_as_float(v.x & 0xFFFF0000u)  * z1a.y;
            d += __uint_as_float(v.y << 16)          * z1a.z;
            d += __uint_as_float(v.y & 0xFFFF0000u)  * z1a.w;
            d += __uint_as_float(v.z << 16)          * z1b.x;
            d += __uint_as_float(v.z & 0xFFFF0000u)  * z1b.y;
            d += __uint_as_float(v.w << 16)          * z1b.z;
            d += __uint_as_float(v.w & 0xFFFF0000u)  * z1b.w;
            d += __shfl_xor_sync(0xffffffffu, d, 4);
            d += __shfl_xor_sync(0xffffffffu, d, 2);
            d += __shfl_xor_sync(0xffffffffu, d, 1);
            if (m == 0) dot_sm[w][myneg] = d;
        }
        __syncwarp();

        // ---- phase 3: cos / clamp / accumulate ----
        #pragma unroll
        for (int r = 0; r < 8; r++) {
            int n = (r << 5) + lane;
            float d    = dot_sm[w][n];
            int   q    = q_sm[w][n];
            float cosv = d * rz1np * rz2n_sm[q];
            acc[r] += fminf(fabsf(cosv * weight), 1.0f);
        }
        if (lane == 0) {
            float c0 = z1sqp / fmaxf(z1sqp, 1e-8f);
            sim0acc += fminf(fabsf(c0), 1.0f);
        }
        __syncwarp();
    }

    // ---- deterministic block-level reduction of per-n sums ----
    #pragma unroll
    for (int r = 0; r < 8; r++) dot_sm[w][(r << 5) + lane] = acc[r];
    if (lane == 0) s0w[w] = sim0acc;
    __syncthreads();

    if (t < NEGn) {
        float s = 0.f;
        #pragma unroll
        for (int k = 0; k < 32; k++) s += dot_sm[k][t];
        g_pn[(((b << 4) + by) << 8) + t] = s;
    }
    if (t == 0) {
        float s = 0.f;
        #pragma unroll
        for (int k = 0; k < 32; k++) s += s0w[k];
        g_s0p[(b << 4) + by] = s;
    }
}

// ---------------- final reduction: 1 block, 1024 threads, fully parallel -----
__global__ void final_kernel(float* __restrict__ out, int out_size) {
    __shared__ float r1[32], r2[32];
    __shared__ float lb[8], s0b[8], s2b[8];
    const int t = threadIdx.x;
    const int b = t >> 7;      // 128 threads per sample
    const int j = t & 127;     // handles negs j and j+128

    float v1 = 0.f, v2 = 0.f;
    #pragma unroll
    for (int h = 0; h < 2; h++) {
        int n = j + (h << 7);
        float s = 0.f;
        #pragma unroll
        for (int k = 0; k < 16; k++) s += g_pn[(((b << 4) + k) << 8) + n];
        float sn = s * (0.5f / 1024.0f);           // mean over p, / TEMP
        v2 += sn;
        v1 += fmaxf(log1pf(-sn), -100.0f);
    }
    #pragma unroll
    for (int s = 16; s > 0; s >>= 1) {
        v1 += __shfl_xor_sync(0xffffffffu, v1, s);
        v2 += __shfl_xor_sync(0xffffffffu, v2, s);
    }
    if ((t & 31) == 0) { r1[t >> 5] = v1; r2[t >> 5] = v2; }
    __syncthreads();

    if (t < 8) {   // one thread per sample
        float s1 = r1[4 * t] + r1[4 * t + 1] + r1[4 * t + 2] + r1[4 * t + 3];
        float s2 = r2[4 * t] + r2[4 * t + 1] + r2[4 * t + 2] + r2[4 * t + 3];
        float s0s = 0.f;
        #pragma unroll
        for (int k = 0; k < 16; k++) s0s += g_s0p[(t << 4) + k];
        float s0   = s0s * (1.0f / 1024.0f);
        float logp = fmaxf(logf(s0), -100.0f);
        lb[t]  = -(logp + s1) * (1.0f / 257.0f);
        s0b[t] = s0;
        s2b[t] = s2;
    }
    __syncthreads();

    if (t == 0) {
        float loss = 0.f, o1 = 0.f, o2 = 0.f;
        #pragma unroll
        for (int i = 0; i < 8; i++) { loss += lb[i]; o1 += s0b[i]; o2 += s2b[i]; }
        if (out_size > 0) out[0] = loss * 0.125f;
        if (out_size > 1) out[1] = o1 * 0.125f;
        if (out_size > 2) out[2] = o2 * (2.0f / (256.0f * 8.0f));
    }
}

// ---------------- launch ------------------------------------------------------
extern "C" void kernel_launch(void* const* d_in, const int* in_sizes, int n_in,
                              void* d_out, int out_size) {
    const float* v1   = (const float*)d_in[0];   // views_1 (8,64,32,32)
    const float* v2   = (const float*)d_in[1];   // views_2 (8,64,32,32)
    const float* img  = (const float*)d_in[2];   // img     (1,3,32,32)
    const int*   nidx = (const int*)  d_in[3];   // neg_idx (8,2,1024,256)

    prep_transpose<<<dim3(32, 8), 256>>>(v1, v2, img);
    main_kernel<<<dim3(Bn, 16), 1024>>>(nidx);
    final_kernel<<<1, 1024>>>((float*)d_out, out_size);
}

// round 4
// speedup vs baseline: 3.0872x; 1.5472x over previous
#include <cuda_runtime.h>
#include <math.h>
#include <stdint.h>

#define Bn   8
#define HWn  1024
#define NEGn 256

// ---------------- device scratch ----------------------------------------------
__device__ __align__(16) unsigned g_z1b[Bn * HWn * 32];   // bf16x2 pixel-major, 128B rows
__device__ __align__(16) unsigned g_z2b[Bn * HWn * 32];
__device__ float g_rz1n[Bn * HWn];
__device__ float g_rz2n[Bn * HWn];
__device__ float g_z1sq[Bn * HWn];
__device__ __align__(16) float4 g_imgt[HWn];
__device__ __align__(16) unsigned short g_gc[(size_t)Bn * HWn * HWn]; // 16MB cos table (bf16)
__device__ float g_pn [Bn * 16 * NEGn];
__device__ float g_s0p[Bn * 16];

__device__ __forceinline__ uint32_t smem_to_u32(const void* p) {
    uint32_t a;
    asm("{ .reg .u64 t; cvta.to.shared.u64 t, %1; cvt.u32.u64 %0, t; }" : "=r"(a) : "l"(p));
    return a;
}
#define SMEM_SWIZZLE_128B(o) ((o) ^ (((o) >> 3) & 0x70))

__device__ __forceinline__ unsigned bf16rn(float f) {
    unsigned u = __float_as_uint(f);
    return (u + 0x7FFFu + ((u >> 16) & 1u)) >> 16;
}

__device__ __forceinline__ void ldsm_x4(uint32_t& r0, uint32_t& r1, uint32_t& r2,
                                        uint32_t& r3, uint32_t addr) {
    asm volatile("ldmatrix.sync.aligned.m8n8.x4.shared.b16 {%0,%1,%2,%3}, [%4];"
                 : "=r"(r0), "=r"(r1), "=r"(r2), "=r"(r3) : "r"(addr));
}
__device__ __forceinline__ void ldsm_x2(uint32_t& r0, uint32_t& r1, uint32_t addr) {
    asm volatile("ldmatrix.sync.aligned.m8n8.x2.shared.b16 {%0,%1}, [%2];"
                 : "=r"(r0), "=r"(r1) : "r"(addr));
}
__device__ __forceinline__ void mma16816(float* c, const uint32_t* a, const uint32_t* b) {
    asm volatile("mma.sync.aligned.m16n8k16.row.col.f32.bf16.bf16.f32 "
                 "{%0,%1,%2,%3}, {%4,%5,%6,%7}, {%8,%9}, {%0,%1,%2,%3};"
                 : "+f"(c[0]), "+f"(c[1]), "+f"(c[2]), "+f"(c[3])
                 : "r"(a[0]), "r"(a[1]), "r"(a[2]), "r"(a[3]), "r"(b[0]), "r"(b[1]));
}

// ---------------- prep: transpose to bf16 pixel-major + norms + img ------------
// grid (32 qtiles, 8 b, 2 views), 256 threads
__global__ void prep_kernel(const float* __restrict__ z1,
                            const float* __restrict__ z2,
                            const float* __restrict__ img) {
    __shared__ float ts[64][33];
    __shared__ float psum[8][32];
    const int s  = blockIdx.z;
    const int b  = blockIdx.y;
    const int q0 = blockIdx.x * 32;
    const int t  = threadIdx.x;
    const int lane = t & 31, wr = t >> 5;

    if (s == 0 && b == 0 && t < 32) {
        int q = q0 + t;
        g_imgt[q] = make_float4(img[q], img[HWn + q], img[2 * HWn + q], 0.f);
    }

    const float* zp = s ? z2 : z1;
    float acc = 0.f;
    #pragma unroll
    for (int k = 0; k < 8; k++) {
        int c = k * 8 + wr;
        float v = zp[((b * 64 + c) << 10) + q0 + lane];
        ts[c][lane] = v;
        acc += v * v;
    }
    psum[wr][lane] = acc;
    __syncthreads();

    if (t < 32) {
        float sum = 0.f;
        #pragma unroll
        for (int i = 0; i < 8; i++) sum += psum[i][t];
        int gi = (b << 10) + q0 + t;
        if (s == 0) { g_z1sq[gi] = sum; g_rz1n[gi] = rsqrtf(sum); }
        else        { g_rz2n[gi] = rsqrtf(sum); }
    }

    unsigned* outp = s ? g_z2b : g_z1b;
    #pragma unroll
    for (int k = 0; k < 4; k++) {
        int idx = k * 256 + t;
        int j = idx >> 5, cp = idx & 31;
        unsigned lo = bf16rn(ts[2 * cp][j]);
        unsigned hi = bf16rn(ts[2 * cp + 1][j]);
        outp[(((b << 10) + q0 + j) << 5) + cp] = lo | (hi << 16);
    }
}

// ---------------- GEMM: G[b][p][q] = cos(z1_p, z2_q) as bf16 -------------------
// mma.sync bf16 HMMA. grid (8 qtile, 8 ptile, 8 b), 256 threads (8 warps, 2x4).
// smem: As 16KB | Bs 16KB | stage 128x272B | rz1s 512B | rz2s 512B
#define SM_AS    0
#define SM_BS    16384
#define SM_STG   32768
#define STG_WPR  68                         // words per stage row (64 + 4 pad)
#define SM_RZ1   (SM_STG + 128 * STG_WPR * 4)   // 67584
#define SM_RZ2   (SM_RZ1 + 512)
#define SM_GEMM_TOTAL (SM_RZ2 + 512)        // 68608

__global__ void __launch_bounds__(256, 1) gemm_kernel() {
    extern __shared__ char smem[];
    const uint32_t sb = smem_to_u32(smem);
    const int t = threadIdx.x, w = t >> 5, lane = t & 31;
    const int qtile = blockIdx.x, ptile = blockIdx.y, b = blockIdx.z;
    const int wm = w >> 2, wn = w & 3;          // warp tile: 64 p x 32 q

    // load A tile (128 p-rows x 128B) and B tile (128 q-rows x 128B), SW128 swizzle
    {
        const uint4* srcA = (const uint4*)g_z1b + (((size_t)(b << 10) + (ptile << 7)) << 3);
        const uint4* srcB = (const uint4*)g_z2b + (((size_t)(b << 10) + (qtile << 7)) << 3);
        #pragma unroll
        for (int it = 0; it < 4; it++) {
            int u = it * 256 + t;
            uint32_t off = SMEM_SWIZZLE_128B((uint32_t)(u * 16));
            *(uint4*)(smem + SM_AS + off) = srcA[u];
            *(uint4*)(smem + SM_BS + off) = srcB[u];
        }
    }
    if (t < 128) {
        ((float*)(smem + SM_RZ1))[t] = g_rz1n[(b << 10) + (ptile << 7) + t];
        ((float*)(smem + SM_RZ2))[t] = g_rz2n[(b << 10) + (qtile << 7) + t];
    }
    __syncthreads();

    float c[4][4][4];
    #pragma unroll
    for (int mi = 0; mi < 4; mi++)
        #pragma unroll
        for (int ni = 0; ni < 4; ni++)
            #pragma unroll
            for (int r = 0; r < 4; r++) c[mi][ni][r] = 0.f;

    #pragma unroll
    for (int ks = 0; ks < 4; ks++) {
        uint32_t a[4][4], bb[4][2];
        #pragma unroll
        for (int mi = 0; mi < 4; mi++) {
            int row  = (wm << 6) + (mi << 4) + (lane & 15);
            int half = lane >> 4;
            uint32_t off = SMEM_SWIZZLE_128B((uint32_t)(row * 128 + ks * 32 + half * 16));
            ldsm_x4(a[mi][0], a[mi][1], a[mi][2], a[mi][3], sb + SM_AS + off);
        }
        #pragma unroll
        for (int ni = 0; ni < 4; ni++) {
            int row  = (wn << 5) + (ni << 3) + (lane & 7);
            int half = (lane >> 3) & 1;
            uint32_t off = SMEM_SWIZZLE_128B((uint32_t)(row * 128 + ks * 32 + half * 16));
            ldsm_x2(bb[ni][0], bb[ni][1], sb + SM_BS + off);
        }
        #pragma unroll
        for (int mi = 0; mi < 4; mi++)
            #pragma unroll
            for (int ni = 0; ni < 4; ni++)
                mma16816(c[mi][ni], a[mi], bb[ni]);
    }
    __syncthreads();   // done with As/Bs region reuse boundary (stage is separate)

    // epilogue: scale, pack bf16x2, write to padded stage
    {
        uint32_t* stg = (uint32_t*)(smem + SM_STG);
        const float* rz1s = (const float*)(smem + SM_RZ1);
        const float* rz2s = (const float*)(smem + SM_RZ2);
        #pragma unroll
        for (int mi = 0; mi < 4; mi++) {
            int r0 = (wm << 6) + (mi << 4) + (lane >> 2);
            int r1 = r0 + 8;
            float z1a = rz1s[r0], z1b = rz1s[r1];
            #pragma unroll
            for (int ni = 0; ni < 4; ni++) {
                int cq = (wn << 5) + (ni << 3) + ((lane & 3) << 1);
                float rq0 = rz2s[cq], rq1 = rz2s[cq + 1];
                uint32_t u0, u1;
                float a0 = c[mi][ni][0] * z1a * rq0, a1 = c[mi][ni][1] * z1a * rq1;
                float b0 = c[mi][ni][2] * z1b * rq0, b1 = c[mi][ni][3] * z1b * rq1;
                asm("cvt.rn.bf16x2.f32 %0, %1, %2;" : "=r"(u0) : "f"(a1), "f"(a0));
                asm("cvt.rn.bf16x2.f32 %0, %1, %2;" : "=r"(u1) : "f"(b1), "f"(b0));
                stg[r0 * STG_WPR + (cq >> 1)] = u0;
                stg[r1 * STG_WPR + (cq >> 1)] = u1;
            }
        }
    }
    __syncthreads();

    // coalesced store: 128 rows x 256B; 16 rows per iteration
    {
        const uint32_t* stg = (const uint32_t*)(smem + SM_STG);
        #pragma unroll
        for (int it = 0; it < 8; it++) {
            int row  = it * 16 + (t >> 4);
            int colw = (t & 15) << 2;
            uint4 v = *(const uint4*)(stg + row * STG_WPR + colw);
            size_t off = ((size_t)(b << 10) + (ptile << 7) + row) << 10;
            *(uint4*)((char*)g_gc + (off + (qtile << 7) + (colw << 1)) * 2) = v;
        }
    }
}

// ---------------- gather: weight + cos-gather + sim accumulate -----------------
__global__ void __launch_bounds__(1024, 1)
gather_kernel(const int* __restrict__ neg_idx) {
    __shared__ float4 imgt_sm[HWn];     // 16 KB
    __shared__ float  dot_sm[32][NEGn]; // 32 KB
    __shared__ float  s0w[32];

    const int b    = blockIdx.x;
    const int by   = blockIdx.y;
    const int t    = threadIdx.x;
    const int w    = t >> 5;
    const int lane = t & 31;

    imgt_sm[t] = g_imgt[t];
    __syncthreads();

    const float INV_EUC   = 1.0f / sqrtf((float)(31 * 31 + 31 * 31));
    const float INV_SQRT3 = 0.57735026919f;

    float acc[8];
    #pragma unroll
    for (int r = 0; r < 8; r++) acc[r] = 0.f;
    float sim0acc = 0.f;

    const unsigned short* gcb = g_gc + ((size_t)b << 20);

    #pragma unroll 1
    for (int it = 0; it < 2; it++) {
        const int p = (by << 6) + (w << 1) + it;
        const float z1sqp = g_z1sq[(b << 10) + p];
        const float hp = (float)(p >> 5), wp = (float)(p & 31);
        const float4 ctr = imgt_sm[p];

        const int* negH = neg_idx + ((size_t)(b * 2) << 18) + (p << 8);
        const int* negW = negH + (1 << 18);

        int qn[8];
        float eucsq = 0.f, rgbsq = 0.f;
        #pragma unroll
        for (int r = 0; r < 8; r++) {
            int n  = (r << 5) + lane;
            int nh = negH[n];
            int nw = negW[n];
            int q  = (nh << 5) + nw;
            qn[r] = q;
            float dh = hp - (float)nh, dw = wp - (float)nw;
            eucsq += dh * dh; eucsq += dw * dw;
            float4 c4 = imgt_sm[q];
            float dr = ctr.x - c4.x, dg = ctr.y - c4.y, db = ctr.z - c4.z;
            rgbsq += dr * dr; rgbsq += dg * dg; rgbsq += db * db;
        }
        #pragma unroll
        for (int s = 16; s > 0; s >>= 1) {
            eucsq += __shfl_xor_sync(0xffffffffu, eucsq, s);
            rgbsq += __shfl_xor_sync(0xffffffffu, rgbsq, s);
        }
        const float weight = 0.8f * sqrtf(eucsq) * INV_EUC
                           + 0.2f * sqrtf(rgbsq) * INV_SQRT3;

        const unsigned short* grow = gcb + ((size_t)p << 10);
        #pragma unroll
        for (int r = 0; r < 8; r++) {
            float cosv = __uint_as_float((unsigned)grow[qn[r]] << 16);
            acc[r] += fminf(fabsf(cosv * weight), 1.0f);
        }
        if (lane == 0) {
            float c0 = z1sqp / fmaxf(z1sqp, 1e-8f);
            sim0acc += fminf(fabsf(c0), 1.0f);
        }
    }

    #pragma unroll
    for (int r = 0; r < 8; r++) dot_sm[w][(r << 5) + lane] = acc[r];
    if (lane == 0) s0w[w] = sim0acc;
    __syncthreads();

    if (t < NEGn) {
        float s = 0.f;
        #pragma unroll
        for (int k = 0; k < 32; k++) s += dot_sm[k][t];
        g_pn[(((b << 4) + by) << 8) + t] = s;
    }
    if (t == 0) {
        float s = 0.f;
        #pragma unroll
        for (int k = 0; k < 32; k++) s += s0w[k];
        g_s0p[(b << 4) + by] = s;
    }
}

// ---------------- final reduction ----------------------------------------------
__global__ void final_kernel(float* __restrict__ out, int out_size) {
    __shared__ float r1[32], r2[32];
    __shared__ float lb[8], s0b[8], s2b[8];
    const int t = threadIdx.x;
    const int b = t >> 7;
    const int j = t & 127;

    float v1 = 0.f, v2 = 0.f;
    #pragma unroll
    for (int h = 0; h < 2; h++) {
        int n = j + (h << 7);
        float s = 0.f;
        #pragma unroll
        for (int k = 0; k < 16; k++) s += g_pn[(((b << 4) + k) << 8) + n];
        float sn = s * (0.5f / 1024.0f);
        v2 += sn;
        v1 += fmaxf(log1pf(-sn), -100.0f);
    }
    #pragma unroll
    for (int s = 16; s > 0; s >>= 1) {
        v1 += __shfl_xor_sync(0xffffffffu, v1, s);
        v2 += __shfl_xor_sync(0xffffffffu, v2, s);
    }
    if ((t & 31) == 0) { r1[t >> 5] = v1; r2[t >> 5] = v2; }
    __syncthreads();

    if (t < 8) {
        float s1 = r1[4 * t] + r1[4 * t + 1] + r1[4 * t + 2] + r1[4 * t + 3];
        float s2 = r2[4 * t] + r2[4 * t + 1] + r2[4 * t + 2] + r2[4 * t + 3];
        float s0s = 0.f;
        #pragma unroll
        for (int k = 0; k < 16; k++) s0s += g_s0p[(t << 4) + k];
        float s0   = s0s * (1.0f / 1024.0f);
        float logp = fmaxf(logf(s0), -100.0f);
        lb[t]  = -(logp + s1) * (1.0f / 257.0f);
        s0b[t] = s0;
        s2b[t] = s2;
    }
    __syncthreads();

    if (t == 0) {
        float loss = 0.f, o1 = 0.f, o2 = 0.f;
        #pragma unroll
        for (int i = 0; i < 8; i++) { loss += lb[i]; o1 += s0b[i]; o2 += s2b[i]; }
        if (out_size > 0) out[0] = loss * 0.125f;
        if (out_size > 1) out[1] = o1 * 0.125f;
        if (out_size > 2) out[2] = o2 * (2.0f / (256.0f * 8.0f));
    }
}

// ---------------- launch --------------------------------------------------------
extern "C" void kernel_launch(void* const* d_in, const int* in_sizes, int n_in,
                              void* d_out, int out_size) {
    const float* v1   = (const float*)d_in[0];
    const float* v2   = (const float*)d_in[1];
    const float* img  = (const float*)d_in[2];
    const int*   nidx = (const int*)  d_in[3];

    cudaFuncSetAttribute(gemm_kernel, cudaFuncAttributeMaxDynamicSharedMemorySize,
                         SM_GEMM_TOTAL);

    prep_kernel<<<dim3(32, 8, 2), 256>>>(v1, v2, img);
    gemm_kernel<<<dim3(8, 8, 8), 256, SM_GEMM_TOTAL>>>();
    gather_kernel<<<dim3(Bn, 16), 1024>>>(nidx);
    final_kernel<<<1, 1024>>>((float*)d_out, out_size);
}